// round 2
// baseline (speedup 1.0000x reference)
#include <cuda_runtime.h>
#include <cstdint>

// FlattenHead: compact valid rows.
// x: [B=16, T=4096, D=1024] fp32. seq_lens: [16] delivered as int32 by harness.
// out[prefix[b] + t] row = x[b, t] for t < seq_lens[b].
//
// One block per (b,t) row. 256 threads x float4 = 4096 bytes = one D-row.
// Prefix over 16 int32 recomputed per block (single cacheline, L2 broadcast).

static constexpr int B = 16;
static constexpr int T = 4096;
static constexpr int D = 1024;            // floats per row
static constexpr int VEC_PER_ROW = D / 4; // 256 float4 per row

__global__ __launch_bounds__(VEC_PER_ROW, 8)
void flatten_head_kernel(const float4* __restrict__ x,
                         const int* __restrict__ seq_lens,
                         float4* __restrict__ out,
                         long long out_vecs)
{
    const int row = blockIdx.x;          // 0 .. B*T-1
    const int b   = row >> 12;           // row / T
    const int t   = row & (T - 1);       // row % T

    const int len = seq_lens[b];
    if (t >= len) return;                // invalid row: nothing to copy

    // Exclusive prefix sum of seq_lens[0..b-1]. 16 int32 = one 64B region,
    // L1/L2 broadcast hits, negligible cost.
    long long prefix = 0;
#pragma unroll
    for (int i = 0; i < B; ++i) {
        if (i < b) prefix += (long long)seq_lens[i];
    }

    const long long src = (long long)row * VEC_PER_ROW + threadIdx.x;
    const long long dst = (prefix + (long long)t) * VEC_PER_ROW + threadIdx.x;
    if (dst < out_vecs)                  // defensive bound (predicated STG)
        out[dst] = x[src];
}

extern "C" void kernel_launch(void* const* d_in, const int* in_sizes, int n_in,
                              void* d_out, int out_size)
{
    // Identify inputs by size: x has B*T*D elements, seq_lens has B.
    const void* p0 = d_in[0];
    const void* p1 = (n_in > 1) ? d_in[1] : d_in[0];
    const float4* x;
    const int*    lens;
    if (in_sizes[0] == B) {              // lens first (unexpected, but handle)
        lens = (const int*)p0;
        x    = (const float4*)p1;
    } else {
        x    = (const float4*)p0;
        lens = (const int*)p1;
    }
    float4* out = (float4*)d_out;
    const long long out_vecs = (long long)out_size / 4;

    flatten_head_kernel<<<B * T, VEC_PER_ROW>>>(x, lens, out, out_vecs);
}

// round 3
// speedup vs baseline: 1.4923x; 1.4923x over previous
#include <cuda_runtime.h>
#include <cstdint>

// FlattenHead: segmented row compaction.
// x: [B=16, T=4096, D=1024] fp32, seq_lens: [16] int32 (harness dtype).
// out rows = concat of x[b, 0:seq_lens[b]] per batch.
//
// R3 design: 8 rows per block (32KB chunk), 256 threads x 8 float4 each.
// All-int32 index math; prefix over 16 lens amortized over 128B/thread.

static constexpr int B = 16;
static constexpr int T = 4096;
static constexpr int VEC_PER_ROW = 256;       // D/4 float4 per row
static constexpr int ROWS_PER_BLK = 8;
static constexpr int VECS_PER_BLK = ROWS_PER_BLK * VEC_PER_ROW;  // 2048
static constexpr int BLKS_PER_BATCH = T / ROWS_PER_BLK;           // 512

__global__ __launch_bounds__(256, 8)
void flatten_head_kernel(const float4* __restrict__ x,
                         const int* __restrict__ seq_lens,
                         float4* __restrict__ out)
{
    const int blk = blockIdx.x;
    const int b   = blk >> 9;                 // / BLKS_PER_BATCH
    const int t0  = (blk & (BLKS_PER_BATCH - 1)) * ROWS_PER_BLK;

    const int len = seq_lens[b];
    if (t0 >= len) return;                    // fully-invalid chunk

    // Exclusive prefix of lens[0..b-1], 32-bit (sum <= 65536).
    int prefix = 0;
#pragma unroll
    for (int i = 0; i < B; ++i)
        prefix += (i < b) ? seq_lens[i] : 0;

    const int tid = threadIdx.x;
    const float4* __restrict__ src = x   + ((b * T + t0) * VEC_PER_ROW);
    float4*       __restrict__ dst = out + ((prefix + t0) * VEC_PER_ROW);

    const int nvalid = min(len - t0, ROWS_PER_BLK) * VEC_PER_ROW;

    if (nvalid == VECS_PER_BLK) {
        // Fast path: front-batch 8 loads (MLP=8), then 8 stores.
        float4 r[ROWS_PER_BLK];
#pragma unroll
        for (int k = 0; k < ROWS_PER_BLK; ++k)
            r[k] = src[tid + k * 256];
#pragma unroll
        for (int k = 0; k < ROWS_PER_BLK; ++k)
            dst[tid + k * 256] = r[k];
    } else {
        // Boundary chunk (at most one per batch): predicated copy.
#pragma unroll
        for (int k = 0; k < ROWS_PER_BLK; ++k) {
            const int idx = tid + k * 256;
            if (idx < nvalid) dst[idx] = src[idx];
        }
    }
}

extern "C" void kernel_launch(void* const* d_in, const int* in_sizes, int n_in,
                              void* d_out, int out_size)
{
    (void)out_size;
    const float4* x;
    const int*    lens;
    if (in_sizes[0] == B) {                   // lens-first ordering (defensive)
        lens = (const int*)d_in[0];
        x    = (const float4*)((n_in > 1) ? d_in[1] : d_in[0]);
    } else {
        x    = (const float4*)d_in[0];
        lens = (const int*)((n_in > 1) ? d_in[1] : d_in[0]);
    }
    float4* out = (float4*)d_out;

    flatten_head_kernel<<<B * BLKS_PER_BATCH, 256>>>(x, lens, out);
}